// round 2
// baseline (speedup 1.0000x reference)
#include <cuda_runtime.h>
#include <cuda_bf16.h>
#include <cstdint>

#define N_NODES 50000
#define E_EDGES 400000
#define DIN     256
#define HF      256   // H*F
#define NH      4
#define FD      64
#define NP      3
#define HID     128
#define NEG     0.2f

// ---------------- scratch (static device globals; no allocation) ----------------
__device__ __align__(16) float g_xw[(size_t)NP * N_NODES * HF];   // per-path x@W
__device__ __align__(16) float g_z [(size_t)NP * N_NODES * HF];   // per-path GAT output
__device__ __align__(16) float g_as[N_NODES * NH];                // alpha_src (current path)
__device__ __align__(16) float g_ad[N_NODES * NH];                // alpha_dst
__device__ __align__(16) float g_s [N_NODES * NH];                // softmax denominator
__device__ float g_wsum[NP];                                      // sum of semantic scores

__device__ __forceinline__ float lrelu(float x) { return x > 0.f ? x : NEG * x; }

// ---------------- tiny: zero accumulators each launch ----------------
__global__ void zero_wsum_k() {
    if (threadIdx.x < NP) g_wsum[threadIdx.x] = 0.f;
}

// ---------------- GEMM: g_xw[p] = h @ gat_W[p]  (128x128x8 tiles, fp32) ----------------
__global__ __launch_bounds__(256) void gemm_k(const float* __restrict__ A,
                                              const float* __restrict__ Wall) {
    const int p  = blockIdx.z;
    const float* B = Wall + (size_t)p * DIN * HF;
    __shared__ float As[8][128];
    __shared__ float Bs[8][128];

    const int tid = threadIdx.x;
    const int tx = tid & 15;       // n group
    const int ty = tid >> 4;       // m group
    const int row0 = blockIdx.y * 128;
    const int col0 = blockIdx.x * 128;

    const int a_row = tid >> 1;          // 0..127
    const int a_col = (tid & 1) * 4;     // 0 or 4
    const int b_row = tid >> 5;          // 0..7
    const int b_col = (tid & 31) * 4;    // 0..124

    float acc[8][8];
    #pragma unroll
    for (int i = 0; i < 8; i++)
        #pragma unroll
        for (int j = 0; j < 8; j++) acc[i][j] = 0.f;

    for (int k0 = 0; k0 < DIN; k0 += 8) {
        float4 av;
        int gr = row0 + a_row;
        if (gr < N_NODES) av = *(const float4*)(A + (size_t)gr * DIN + k0 + a_col);
        else av = make_float4(0.f, 0.f, 0.f, 0.f);
        As[a_col + 0][a_row] = av.x;
        As[a_col + 1][a_row] = av.y;
        As[a_col + 2][a_row] = av.z;
        As[a_col + 3][a_row] = av.w;

        float4 bv = *(const float4*)(B + (size_t)(k0 + b_row) * HF + col0 + b_col);
        *(float4*)(&Bs[b_row][b_col]) = bv;
        __syncthreads();

        #pragma unroll
        for (int k = 0; k < 8; k++) {
            float ra[8], rb[8];
            #pragma unroll
            for (int i = 0; i < 8; i++) ra[i] = As[k][ty + i * 16];
            #pragma unroll
            for (int j = 0; j < 8; j++) rb[j] = Bs[k][tx + j * 16];
            #pragma unroll
            for (int i = 0; i < 8; i++)
                #pragma unroll
                for (int j = 0; j < 8; j++) acc[i][j] += ra[i] * rb[j];
        }
        __syncthreads();
    }

    float* out = g_xw + (size_t)p * N_NODES * HF;
    #pragma unroll
    for (int i = 0; i < 8; i++) {
        int gr = row0 + ty + i * 16;
        if (gr < N_NODES) {
            float* dst = out + (size_t)gr * HF + col0;
            #pragma unroll
            for (int j = 0; j < 8; j++) dst[tx + j * 16] = acc[i][j];
        }
    }
}

// ---------------- alpha_src/alpha_dst + self-loop exp into s ----------------
__global__ void alpha_k(const float* __restrict__ asrc, const float* __restrict__ adst, int p) {
    int idx = blockIdx.x * blockDim.x + threadIdx.x;   // over N*NH
    if (idx >= N_NODES * NH) return;
    int n = idx >> 2, h = idx & 3;
    const float* xr = g_xw + (size_t)p * N_NODES * HF + (size_t)n * HF + h * FD;
    const float* sa = asrc + h * FD;
    const float* da = adst + h * FD;
    float ss = 0.f, sd = 0.f;
    #pragma unroll
    for (int f4 = 0; f4 < FD; f4 += 4) {
        float4 x = *(const float4*)(xr + f4);
        float4 a = *(const float4*)(sa + f4);
        float4 d = *(const float4*)(da + f4);
        ss += x.x * a.x + x.y * a.y + x.z * a.z + x.w * a.w;
        sd += x.x * d.x + x.y * d.y + x.z * d.z + x.w * d.w;
    }
    g_as[idx] = ss;
    g_ad[idx] = sd;
    g_s[idx] = __expf(lrelu(ss + sd));   // self-loop term initializes denominator
}

// ---------------- edge pass 1: accumulate exp(e) into denominators ----------------
__global__ void edge_sum_k(const int* __restrict__ ei) {
    int e = blockIdx.x * blockDim.x + threadIdx.x;
    if (e >= E_EDGES) return;
    int src = ei[e];
    int dst = ei[E_EDGES + e];
    float4 a = *(const float4*)&g_as[src * NH];
    float4 d = *(const float4*)&g_ad[dst * NH];
    atomicAdd(&g_s[dst * NH + 0], __expf(lrelu(a.x + d.x)));
    atomicAdd(&g_s[dst * NH + 1], __expf(lrelu(a.y + d.y)));
    atomicAdd(&g_s[dst * NH + 2], __expf(lrelu(a.z + d.z)));
    atomicAdd(&g_s[dst * NH + 3], __expf(lrelu(a.w + d.w)));
}

// ---------------- z init: self-loop contribution + bias ----------------
__global__ void zinit_k(const float* __restrict__ bias, int p) {
    int idx = blockIdx.x * blockDim.x + threadIdx.x;   // over N*64 float4s
    if (idx >= N_NODES * (HF / 4)) return;
    int n = idx >> 6;
    int c = (idx & 63) * 4;
    int h = c >> 6;
    float es = __expf(lrelu(g_as[n * NH + h] + g_ad[n * NH + h]));
    float al = es / g_s[n * NH + h];
    const float* xr = g_xw + (size_t)p * N_NODES * HF + (size_t)n * HF + c;
    float4 x = *(const float4*)xr;
    float4 b = *(const float4*)(bias + c);
    float4 o;
    o.x = al * x.x + b.x; o.y = al * x.y + b.y;
    o.z = al * x.z + b.z; o.w = al * x.w + b.w;
    *(float4*)(g_z + (size_t)p * N_NODES * HF + (size_t)n * HF + c) = o;
}

// ---------------- edge pass 2: weighted scatter of xw[src] into z[dst] (warp per edge) ----------------
__global__ __launch_bounds__(256) void edge_agg_k(const int* __restrict__ ei, int p) {
    int gid = blockIdx.x * blockDim.x + threadIdx.x;
    int e = gid >> 5;
    int lane = gid & 31;
    if (e >= E_EDGES) return;
    int src = ei[e];
    int dst = ei[E_EDGES + e];
    float4 a = *(const float4*)&g_as[src * NH];
    float4 d = *(const float4*)&g_ad[dst * NH];
    float4 s = *(const float4*)&g_s[dst * NH];
    float w[4];
    w[0] = __expf(lrelu(a.x + d.x)) / s.x;
    w[1] = __expf(lrelu(a.y + d.y)) / s.y;
    w[2] = __expf(lrelu(a.z + d.z)) / s.z;
    w[3] = __expf(lrelu(a.w + d.w)) / s.w;

    const float* xs = g_xw + (size_t)p * N_NODES * HF + (size_t)src * HF;
    float* zd = g_z + (size_t)p * N_NODES * HF + (size_t)dst * HF;
    #pragma unroll
    for (int u = 0; u < 2; u++) {
        int c = lane * 8 + u * 4;      // 0..255, head constant within float4
        float ww = w[c >> 6];
        float4 x = *(const float4*)(xs + c);
        atomicAdd(zd + c + 0, ww * x.x);
        atomicAdd(zd + c + 1, ww * x.y);
        atomicAdd(zd + c + 2, ww * x.z);
        atomicAdd(zd + c + 3, ww * x.w);
    }
}

// ---------------- semantic attention score sum (block per node) ----------------
__global__ __launch_bounds__(128) void sem_k(const float* __restrict__ w1,
                                             const float* __restrict__ b1,
                                             const float* __restrict__ w2, int p) {
    int n = blockIdx.x;
    int t = threadIdx.x;   // 0..127, one hidden unit each
    __shared__ float zrow[HF];
    __shared__ float red[4];
    const float* z = g_z + (size_t)p * N_NODES * HF + (size_t)n * HF;
    zrow[t] = z[t];
    zrow[t + 128] = z[t + 128];
    __syncthreads();
    float acc = b1[t];
    #pragma unroll 8
    for (int r = 0; r < HF; r++) acc += zrow[r] * w1[r * HID + t];
    float v = tanhf(acc) * w2[t];
    #pragma unroll
    for (int o = 16; o > 0; o >>= 1) v += __shfl_down_sync(0xffffffffu, v, o);
    if ((t & 31) == 0) red[t >> 5] = v;
    __syncthreads();
    if (t == 0) atomicAdd(&g_wsum[p], red[0] + red[1] + red[2] + red[3]);
}

// ---------------- final: softmax over path means, combine ----------------
__global__ void final_k(float* __restrict__ out) {
    int idx = blockIdx.x * blockDim.x + threadIdx.x;   // over N*64 float4s
    if (idx >= N_NODES * (HF / 4)) return;
    float m0 = g_wsum[0] * (1.f / N_NODES);
    float m1 = g_wsum[1] * (1.f / N_NODES);
    float m2 = g_wsum[2] * (1.f / N_NODES);
    float mm = fmaxf(m0, fmaxf(m1, m2));
    float e0 = __expf(m0 - mm), e1 = __expf(m1 - mm), e2 = __expf(m2 - mm);
    float inv = 1.f / (e0 + e1 + e2);
    float b0 = e0 * inv, b1 = e1 * inv, b2 = e2 * inv;

    size_t off = (size_t)idx * 4;
    float4 z0 = *(const float4*)(g_z + off);
    float4 z1 = *(const float4*)(g_z + (size_t)N_NODES * HF + off);
    float4 z2 = *(const float4*)(g_z + (size_t)2 * N_NODES * HF + off);
    float4 o;
    o.x = b0 * z0.x + b1 * z1.x + b2 * z2.x;
    o.y = b0 * z0.y + b1 * z1.y + b2 * z2.y;
    o.z = b0 * z0.z + b1 * z1.z + b2 * z2.z;
    o.w = b0 * z0.w + b1 * z1.w + b2 * z2.w;
    *(float4*)(out + off) = o;
}

// ---------------- launch ----------------
extern "C" void kernel_launch(void* const* d_in, const int* in_sizes, int n_in,
                              void* d_out, int out_size) {
    const float* h        = (const float*)d_in[0];
    const int* ei[NP] = { (const int*)d_in[1],
                          (const int*)d_in[2],
                          (const int*)d_in[3] };
    const float* gat_W    = (const float*)d_in[4];
    const float* att_src  = (const float*)d_in[5];
    const float* att_dst  = (const float*)d_in[6];
    const float* gat_bias = (const float*)d_in[7];
    const float* sa_w1    = (const float*)d_in[8];
    const float* sa_b1    = (const float*)d_in[9];
    const float* sa_w2    = (const float*)d_in[10];
    float* out = (float*)d_out;

    zero_wsum_k<<<1, 32>>>();

    dim3 ggrid(HF / 128, (N_NODES + 127) / 128, NP);
    gemm_k<<<ggrid, 256>>>(h, gat_W);

    const int nh_blocks   = (N_NODES * NH + 255) / 256;
    const int e_blocks    = (E_EDGES + 255) / 256;
    const int v4_blocks   = (N_NODES * (HF / 4) + 255) / 256;
    const int agg_blocks  = (E_EDGES * 32 + 255) / 256;

    for (int p = 0; p < NP; p++) {
        alpha_k<<<nh_blocks, 256>>>(att_src + p * NH * FD, att_dst + p * NH * FD, p);
        edge_sum_k<<<e_blocks, 256>>>(ei[p]);
        zinit_k<<<v4_blocks, 256>>>(gat_bias + p * HF, p);
        edge_agg_k<<<agg_blocks, 256>>>(ei[p], p);
        sem_k<<<N_NODES, 128>>>(sa_w1, sa_b1, sa_w2, p);
    }

    final_k<<<v4_blocks, 256>>>(out);
}

// round 3
// speedup vs baseline: 1.9178x; 1.9178x over previous
#include <cuda_runtime.h>
#include <cuda_bf16.h>
#include <cstdint>

#define N_NODES 50000
#define E_EDGES 400000
#define DIN     256
#define HF      256   // H*F
#define NH      4
#define FD      64
#define NP      3
#define HID     128
#define NEG     0.2f
#define NPN     (NP * N_NODES)

// ---------------- scratch (static device globals; no allocation) ----------------
__device__ __align__(16) float g_xw[(size_t)NP * N_NODES * HF];   // per-path x@W
__device__ __align__(16) float g_z [(size_t)NP * N_NODES * HF];   // per-path GAT output
__device__ __align__(16) float g_as[NPN * NH];                    // alpha_src per path/node/head
__device__ __align__(16) float g_ad[NPN * NH];                    // alpha_dst
__device__ int   g_cnt[NPN];        // histogram
__device__ int   g_off[NPN];        // CSR begin offsets (global across paths)
__device__ int   g_cur[NPN];        // scatter cursor -> becomes end offsets
__device__ int   g_srcs[(size_t)NP * E_EDGES];   // CSR src lists
__device__ float g_wsum[NP];

__device__ __forceinline__ float lrelu(float x) { return x > 0.f ? x : NEG * x; }

// ---------------- zero counters ----------------
__global__ void zero_k() {
    int i = blockIdx.x * blockDim.x + threadIdx.x;
    if (i < NPN) g_cnt[i] = 0;
    if (i < NP) g_wsum[i] = 0.f;
}

// ---------------- histogram of dst ----------------
__global__ void hist_k(const int* __restrict__ e0, const int* __restrict__ e1,
                       const int* __restrict__ e2) {
    int idx = blockIdx.x * blockDim.x + threadIdx.x;
    if (idx >= NP * E_EDGES) return;
    int p = idx / E_EDGES, e = idx - p * E_EDGES;
    const int* ei = (p == 0) ? e0 : (p == 1) ? e1 : e2;
    int dst = ei[E_EDGES + e];
    atomicAdd(&g_cnt[p * N_NODES + dst], 1);
}

// ---------------- single-block exclusive scan over NPN counters ----------------
__global__ __launch_bounds__(1024) void scan_k() {
    __shared__ float dummy;  (void)dummy;
    __shared__ int sums[1024];
    const int t = threadIdx.x;
    const int chunk = (NPN + 1023) / 1024;   // 147
    int b = t * chunk, e = min(b + chunk, NPN);
    int s = 0;
    for (int i = b; i < e; i++) s += g_cnt[i];
    sums[t] = s;
    __syncthreads();
    // inclusive Hillis-Steele scan on 1024
    for (int o = 1; o < 1024; o <<= 1) {
        int v = (t >= o) ? sums[t - o] : 0;
        __syncthreads();
        sums[t] += v;
        __syncthreads();
    }
    int run = (t == 0) ? 0 : sums[t - 1];    // exclusive base for this chunk
    for (int i = b; i < e; i++) {
        int c = g_cnt[i];
        g_off[i] = run;
        g_cur[i] = run;
        run += c;
    }
}

// ---------------- scatter src into CSR ----------------
__global__ void scatter_k(const int* __restrict__ e0, const int* __restrict__ e1,
                          const int* __restrict__ e2) {
    int idx = blockIdx.x * blockDim.x + threadIdx.x;
    if (idx >= NP * E_EDGES) return;
    int p = idx / E_EDGES, e = idx - p * E_EDGES;
    const int* ei = (p == 0) ? e0 : (p == 1) ? e1 : e2;
    int src = ei[e];
    int dst = ei[E_EDGES + e];
    int pos = atomicAdd(&g_cur[p * N_NODES + dst], 1);
    g_srcs[pos] = src;
}

// ---------------- GEMM: g_xw[p] = h @ gat_W[p]  (128x128x8 tiles, fp32) ----------------
__global__ __launch_bounds__(256) void gemm_k(const float* __restrict__ A,
                                              const float* __restrict__ Wall) {
    const int p  = blockIdx.z;
    const float* B = Wall + (size_t)p * DIN * HF;
    __shared__ float As[8][128];
    __shared__ float Bs[8][128];

    const int tid = threadIdx.x;
    const int tx = tid & 15;
    const int ty = tid >> 4;
    const int row0 = blockIdx.y * 128;
    const int col0 = blockIdx.x * 128;

    const int a_row = tid >> 1;
    const int a_col = (tid & 1) * 4;
    const int b_row = tid >> 5;
    const int b_col = (tid & 31) * 4;

    float acc[8][8];
    #pragma unroll
    for (int i = 0; i < 8; i++)
        #pragma unroll
        for (int j = 0; j < 8; j++) acc[i][j] = 0.f;

    for (int k0 = 0; k0 < DIN; k0 += 8) {
        float4 av;
        int gr = row0 + a_row;
        if (gr < N_NODES) av = *(const float4*)(A + (size_t)gr * DIN + k0 + a_col);
        else av = make_float4(0.f, 0.f, 0.f, 0.f);
        As[a_col + 0][a_row] = av.x;
        As[a_col + 1][a_row] = av.y;
        As[a_col + 2][a_row] = av.z;
        As[a_col + 3][a_row] = av.w;

        float4 bv = *(const float4*)(B + (size_t)(k0 + b_row) * HF + col0 + b_col);
        *(float4*)(&Bs[b_row][b_col]) = bv;
        __syncthreads();

        #pragma unroll
        for (int k = 0; k < 8; k++) {
            float ra[8], rb[8];
            #pragma unroll
            for (int i = 0; i < 8; i++) ra[i] = As[k][ty + i * 16];
            #pragma unroll
            for (int j = 0; j < 8; j++) rb[j] = Bs[k][tx + j * 16];
            #pragma unroll
            for (int i = 0; i < 8; i++)
                #pragma unroll
                for (int j = 0; j < 8; j++) acc[i][j] += ra[i] * rb[j];
        }
        __syncthreads();
    }

    float* out = g_xw + (size_t)p * N_NODES * HF;
    #pragma unroll
    for (int i = 0; i < 8; i++) {
        int gr = row0 + ty + i * 16;
        if (gr < N_NODES) {
            float* dst = out + (size_t)gr * HF + col0;
            #pragma unroll
            for (int j = 0; j < 8; j++) dst[tx + j * 16] = acc[i][j];
        }
    }
}

// ---------------- alpha_src / alpha_dst for all paths ----------------
__global__ void alpha_k(const float* __restrict__ asrc, const float* __restrict__ adst) {
    int idx = blockIdx.x * blockDim.x + threadIdx.x;   // over NPN*NH
    if (idx >= NPN * NH) return;
    int ng = idx >> 2, h = idx & 3;
    int p = ng / N_NODES;
    const float* xr = g_xw + (size_t)ng * HF + h * FD;
    const float* sa = asrc + p * NH * FD + h * FD;
    const float* da = adst + p * NH * FD + h * FD;
    float ss = 0.f, sd = 0.f;
    #pragma unroll
    for (int f4 = 0; f4 < FD; f4 += 4) {
        float4 x = *(const float4*)(xr + f4);
        float4 a = *(const float4*)(sa + f4);
        float4 d = *(const float4*)(da + f4);
        ss += x.x * a.x + x.y * a.y + x.z * a.z + x.w * a.w;
        sd += x.x * d.x + x.y * d.y + x.z * d.z + x.w * d.w;
    }
    g_as[idx] = ss;
    g_ad[idx] = sd;
}

// ---------------- CSR aggregation: block per (node, path), no atomics ----------------
#define CHUNK 128
__global__ __launch_bounds__(64) void agg_k(const float* __restrict__ bias_all) {
    const int n = blockIdx.x;
    const int p = blockIdx.y;
    const int t = threadIdx.x;
    __shared__ int    s_src[CHUNK];
    __shared__ float4 s_w[CHUNK];
    __shared__ float4 s_red[64];

    const size_t ng = (size_t)p * N_NODES + n;
    const int beg = g_off[ng];
    const int end = g_cur[ng];
    const float4 ad4 = *(const float4*)&g_ad[ng * NH];
    const float4 asn = *(const float4*)&g_as[ng * NH];
    const float* asp = g_as + (size_t)p * N_NODES * NH;
    const float* xwp = g_xw + (size_t)p * N_NODES * HF;

    // pass A: softmax denominator per head
    float4 acc = make_float4(0.f, 0.f, 0.f, 0.f);
    for (int j = beg + t; j < end; j += 64) {
        int src = g_srcs[j];
        float4 a = *(const float4*)&asp[src * NH];
        acc.x += __expf(lrelu(a.x + ad4.x));
        acc.y += __expf(lrelu(a.y + ad4.y));
        acc.z += __expf(lrelu(a.z + ad4.z));
        acc.w += __expf(lrelu(a.w + ad4.w));
    }
    s_red[t] = acc;
    __syncthreads();
    #pragma unroll
    for (int o = 32; o > 0; o >>= 1) {
        if (t < o) {
            float4 b = s_red[t + o];
            float4 a = s_red[t];
            a.x += b.x; a.y += b.y; a.z += b.z; a.w += b.w;
            s_red[t] = a;
        }
        __syncthreads();
    }
    float4 es;  // self-loop exp
    es.x = __expf(lrelu(asn.x + ad4.x));
    es.y = __expf(lrelu(asn.y + ad4.y));
    es.z = __expf(lrelu(asn.z + ad4.z));
    es.w = __expf(lrelu(asn.w + ad4.w));
    float4 sden = s_red[0];
    float4 inv4;
    inv4.x = 1.f / (sden.x + es.x);
    inv4.y = 1.f / (sden.y + es.y);
    inv4.z = 1.f / (sden.z + es.z);
    inv4.w = 1.f / (sden.w + es.w);
    __syncthreads();

    // pass B: weighted aggregation; thread owns 4 output channels
    const int c = t * 4;
    const int head = c >> 6;
    const float invh = ((const float*)&inv4)[head];
    const float selfw = ((const float*)&es)[head] * invh;

    float4 x4 = *(const float4*)(xwp + (size_t)n * HF + c);
    float4 accz;
    accz.x = selfw * x4.x; accz.y = selfw * x4.y;
    accz.z = selfw * x4.z; accz.w = selfw * x4.w;

    for (int base = beg; base < end; base += CHUNK) {
        int cn = min(CHUNK, end - base);
        for (int jj = t; jj < cn; jj += 64) {
            int src = g_srcs[base + jj];
            s_src[jj] = src;
            float4 a = *(const float4*)&asp[src * NH];
            float4 w;
            w.x = __expf(lrelu(a.x + ad4.x)) * inv4.x;
            w.y = __expf(lrelu(a.y + ad4.y)) * inv4.y;
            w.z = __expf(lrelu(a.z + ad4.z)) * inv4.z;
            w.w = __expf(lrelu(a.w + ad4.w)) * inv4.w;
            s_w[jj] = w;
        }
        __syncthreads();
        for (int jj = 0; jj < cn; jj++) {
            float ww = ((const float*)&s_w[jj])[head];
            float4 x = *(const float4*)(xwp + (size_t)s_src[jj] * HF + c);
            accz.x += ww * x.x; accz.y += ww * x.y;
            accz.z += ww * x.z; accz.w += ww * x.w;
        }
        __syncthreads();
    }

    float4 b4 = *(const float4*)(bias_all + p * HF + c);
    accz.x += b4.x; accz.y += b4.y; accz.z += b4.z; accz.w += b4.w;
    *(float4*)(g_z + ng * HF + c) = accz;
}

// ---------------- semantic GEMM: [NPN,256]@[256,128] with fused tanh-dot-reduce ----------------
__global__ __launch_bounds__(256) void sem_gemm_k(const float* __restrict__ w1,
                                                  const float* __restrict__ b1,
                                                  const float* __restrict__ w2) {
    __shared__ float As[8][128];
    __shared__ float Bs[8][128];
    __shared__ float s_w3[NP];

    const int tid = threadIdx.x;
    const int tx = tid & 15;
    const int ty = tid >> 4;
    const int row0 = blockIdx.y * 128;

    const int a_row = tid >> 1;
    const int a_col = (tid & 1) * 4;
    const int b_row = tid >> 5;
    const int b_col = (tid & 31) * 4;

    if (tid < NP) s_w3[tid] = 0.f;

    float acc[8][8];
    #pragma unroll
    for (int i = 0; i < 8; i++)
        #pragma unroll
        for (int j = 0; j < 8; j++) acc[i][j] = 0.f;

    for (int k0 = 0; k0 < HF; k0 += 8) {
        float4 av;
        int gr = row0 + a_row;
        if (gr < NPN) av = *(const float4*)(g_z + (size_t)gr * HF + k0 + a_col);
        else av = make_float4(0.f, 0.f, 0.f, 0.f);
        As[a_col + 0][a_row] = av.x;
        As[a_col + 1][a_row] = av.y;
        As[a_col + 2][a_row] = av.z;
        As[a_col + 3][a_row] = av.w;

        float4 bv = *(const float4*)(w1 + (size_t)(k0 + b_row) * HID + b_col);
        *(float4*)(&Bs[b_row][b_col]) = bv;
        __syncthreads();

        #pragma unroll
        for (int k = 0; k < 8; k++) {
            float ra[8], rb[8];
            #pragma unroll
            for (int i = 0; i < 8; i++) ra[i] = As[k][ty + i * 16];
            #pragma unroll
            for (int j = 0; j < 8; j++) rb[j] = Bs[k][tx + j * 16];
            #pragma unroll
            for (int i = 0; i < 8; i++)
                #pragma unroll
                for (int j = 0; j < 8; j++) acc[i][j] += ra[i] * rb[j];
        }
        __syncthreads();
    }

    // epilogue: per-row partial of tanh(acc + b1) . w2, reduced per path
    float b1v[8], w2v[8];
    #pragma unroll
    for (int j = 0; j < 8; j++) {
        int cj = tx + j * 16;
        b1v[j] = b1[cj];
        w2v[j] = w2[cj];
    }
    #pragma unroll
    for (int i = 0; i < 8; i++) {
        int gr = row0 + ty + i * 16;
        if (gr < NPN) {
            int pi = gr / N_NODES;
            float v = 0.f;
            #pragma unroll
            for (int j = 0; j < 8; j++)
                v += tanhf(acc[i][j] + b1v[j]) * w2v[j];
            atomicAdd(&s_w3[pi], v);
        }
    }
    __syncthreads();
    if (tid < NP) atomicAdd(&g_wsum[tid], s_w3[tid]);
}

// ---------------- final: softmax over path means, combine ----------------
__global__ void final_k(float* __restrict__ out) {
    int idx = blockIdx.x * blockDim.x + threadIdx.x;   // over N*64 float4s
    if (idx >= N_NODES * (HF / 4)) return;
    float m0 = g_wsum[0] * (1.f / N_NODES);
    float m1 = g_wsum[1] * (1.f / N_NODES);
    float m2 = g_wsum[2] * (1.f / N_NODES);
    float mm = fmaxf(m0, fmaxf(m1, m2));
    float e0 = __expf(m0 - mm), e1 = __expf(m1 - mm), e2 = __expf(m2 - mm);
    float inv = 1.f / (e0 + e1 + e2);
    float b0 = e0 * inv, b1 = e1 * inv, b2 = e2 * inv;

    size_t off = (size_t)idx * 4;
    float4 z0 = *(const float4*)(g_z + off);
    float4 z1 = *(const float4*)(g_z + (size_t)N_NODES * HF + off);
    float4 z2 = *(const float4*)(g_z + (size_t)2 * N_NODES * HF + off);
    float4 o;
    o.x = b0 * z0.x + b1 * z1.x + b2 * z2.x;
    o.y = b0 * z0.y + b1 * z1.y + b2 * z2.y;
    o.z = b0 * z0.z + b1 * z1.z + b2 * z2.z;
    o.w = b0 * z0.w + b1 * z1.w + b2 * z2.w;
    *(float4*)(out + off) = o;
}

// ---------------- launch ----------------
extern "C" void kernel_launch(void* const* d_in, const int* in_sizes, int n_in,
                              void* d_out, int out_size) {
    const float* h        = (const float*)d_in[0];
    const int* e0         = (const int*)d_in[1];
    const int* e1         = (const int*)d_in[2];
    const int* e2         = (const int*)d_in[3];
    const float* gat_W    = (const float*)d_in[4];
    const float* att_src  = (const float*)d_in[5];
    const float* att_dst  = (const float*)d_in[6];
    const float* gat_bias = (const float*)d_in[7];
    const float* sa_w1    = (const float*)d_in[8];
    const float* sa_b1    = (const float*)d_in[9];
    const float* sa_w2    = (const float*)d_in[10];
    float* out = (float*)d_out;

    zero_k<<<(NPN + 255) / 256, 256>>>();
    hist_k<<<(NP * E_EDGES + 255) / 256, 256>>>(e0, e1, e2);
    scan_k<<<1, 1024>>>();
    scatter_k<<<(NP * E_EDGES + 255) / 256, 256>>>(e0, e1, e2);

    dim3 ggrid(HF / 128, (N_NODES + 127) / 128, NP);
    gemm_k<<<ggrid, 256>>>(h, gat_W);

    alpha_k<<<(NPN * NH + 255) / 256, 256>>>(att_src, att_dst);

    dim3 agrid(N_NODES, NP);
    agg_k<<<agrid, 64>>>(gat_bias);

    dim3 sgrid(1, (NPN + 127) / 128);
    sem_gemm_k<<<sgrid, 256>>>(sa_w1, sa_b1, sa_w2);

    final_k<<<(N_NODES * (HF / 4) + 255) / 256, 256>>>(out);
}

// round 9
// speedup vs baseline: 3.2837x; 1.7122x over previous
#include <cuda_runtime.h>
#include <cuda_bf16.h>
#include <cstdint>

#define N_NODES 50000
#define E_EDGES 400000
#define DIN     256
#define HF      256
#define NH      4
#define FD      64
#define NP      3
#define HID     128
#define NEG     0.2f
#define NPN     (NP * N_NODES)
#define K3      768     // [hi | lo | hi] concatenated K for feature GEMM

// ================= scratch (static device globals) =================
__device__ __align__(16) float g_xw[(size_t)NP * N_NODES * HF];
__device__ __align__(16) float g_z [(size_t)NP * N_NODES * HF];
__device__ __align__(16) float g_as[NPN * NH];
__device__ __align__(16) float g_ad[NPN * NH];
__device__ int   g_cnt[NPN];
__device__ int   g_off[NPN];
__device__ int   g_cur[NPN];
__device__ int   g_srcs[(size_t)NP * E_EDGES];
__device__ float g_wsum[NP];
__device__ __align__(16) __nv_bfloat16 g_h3 [(size_t)N_NODES * K3];   // h  [hi|lo|hi]
__device__ __align__(16) __nv_bfloat16 g_w3t[(size_t)NP * HF * K3];   // W^T [hi|hi|lo]  [p][n][k]
__device__ __align__(16) __nv_bfloat16 g_w1t[(size_t)HID * HF];       // w1^T bf16 [n][k]
__device__ __align__(16) __nv_bfloat16 g_zb [(size_t)NPN * HF];       // z bf16

__device__ __forceinline__ float lrelu(float x) { return x > 0.f ? x : NEG * x; }
__device__ __forceinline__ uint32_t smem_u32(const void* p) {
    uint32_t a;
    asm("{ .reg .u64 t; cvta.to.shared.u64 t, %1; cvt.u32.u64 %0, t; }" : "=r"(a) : "l"(p));
    return a;
}
#define SWZ128(o) ((o) ^ (((o) >> 3) & 0x70))

__device__ __forceinline__ void ldsm_x4(uint32_t& r0, uint32_t& r1, uint32_t& r2, uint32_t& r3,
                                        uint32_t addr) {
    asm volatile("ldmatrix.sync.aligned.m8n8.x4.shared.b16 {%0,%1,%2,%3}, [%4];"
                 : "=r"(r0), "=r"(r1), "=r"(r2), "=r"(r3) : "r"(addr));
}
__device__ __forceinline__ void mma16816(float* c, const uint32_t* a, uint32_t b0, uint32_t b1) {
    asm volatile("mma.sync.aligned.m16n8k16.row.col.f32.bf16.bf16.f32 "
                 "{%0,%1,%2,%3}, {%4,%5,%6,%7}, {%8,%9}, {%0,%1,%2,%3};"
                 : "+f"(c[0]), "+f"(c[1]), "+f"(c[2]), "+f"(c[3])
                 : "r"(a[0]), "r"(a[1]), "r"(a[2]), "r"(a[3]), "r"(b0), "r"(b1));
}

// ================= CSR setup =================
__global__ void zero_k() {
    int i = blockIdx.x * blockDim.x + threadIdx.x;
    if (i < NPN) g_cnt[i] = 0;
    if (i < NP) g_wsum[i] = 0.f;
}
__global__ void hist_k(const int* __restrict__ e0, const int* __restrict__ e1,
                       const int* __restrict__ e2) {
    int idx = blockIdx.x * blockDim.x + threadIdx.x;
    if (idx >= NP * E_EDGES) return;
    int p = idx / E_EDGES, e = idx - p * E_EDGES;
    const int* ei = (p == 0) ? e0 : (p == 1) ? e1 : e2;
    atomicAdd(&g_cnt[p * N_NODES + ei[E_EDGES + e]], 1);
}
__global__ __launch_bounds__(1024) void scan_k() {
    __shared__ int sums[1024];
    const int t = threadIdx.x;
    const int chunk = (NPN + 1023) / 1024;
    int b = t * chunk, e = min(b + chunk, NPN);
    int s = 0;
    for (int i = b; i < e; i++) s += g_cnt[i];
    sums[t] = s;
    __syncthreads();
    for (int o = 1; o < 1024; o <<= 1) {
        int v = (t >= o) ? sums[t - o] : 0;
        __syncthreads();
        sums[t] += v;
        __syncthreads();
    }
    int run = (t == 0) ? 0 : sums[t - 1];
    for (int i = b; i < e; i++) {
        int c = g_cnt[i];
        g_off[i] = run; g_cur[i] = run; run += c;
    }
}
__global__ void scatter_k(const int* __restrict__ e0, const int* __restrict__ e1,
                          const int* __restrict__ e2) {
    int idx = blockIdx.x * blockDim.x + threadIdx.x;
    if (idx >= NP * E_EDGES) return;
    int p = idx / E_EDGES, e = idx - p * E_EDGES;
    const int* ei = (p == 0) ? e0 : (p == 1) ? e1 : e2;
    int pos = atomicAdd(&g_cur[p * N_NODES + ei[E_EDGES + e]], 1);
    g_srcs[pos] = ei[e];
}

// ================= fp32 -> bf16 split conversions =================
__global__ void conv_h_k(const float* __restrict__ h) {
    int i = blockIdx.x * blockDim.x + threadIdx.x;
    if (i >= N_NODES * DIN) return;
    int row = i >> 8, k = i & 255;
    float f = h[i];
    __nv_bfloat16 hi = __float2bfloat16(f);
    __nv_bfloat16 lo = __float2bfloat16(f - __bfloat162float(hi));
    size_t base = (size_t)row * K3 + k;
    g_h3[base] = hi;           // seg0: hi (x Bhi)
    g_h3[base + 256] = lo;     // seg1: lo (x Bhi)
    g_h3[base + 512] = hi;     // seg2: hi (x Blo)
}
__global__ void conv_w_k(const float* __restrict__ W, const float* __restrict__ w1) {
    int i = blockIdx.x * blockDim.x + threadIdx.x;
    if (i < NP * DIN * HF) {               // [p][n][k] <- W[p][k][n]
        int p = i >> 16, rem = i & 65535, n = rem >> 8, k = rem & 255;
        float f = W[p * 65536 + k * 256 + n];
        __nv_bfloat16 hi = __float2bfloat16(f);
        __nv_bfloat16 lo = __float2bfloat16(f - __bfloat162float(hi));
        size_t base = (size_t)p * HF * K3 + (size_t)n * K3 + k;
        g_w3t[base] = hi;          // seg0: hi
        g_w3t[base + 256] = hi;    // seg1: hi
        g_w3t[base + 512] = lo;    // seg2: lo
    } else {
        int j = i - NP * DIN * HF;
        if (j < HID * HF) {                // [n][k] <- w1[k][n]
            int n = j >> 8, k = j & 255;
            g_w1t[(size_t)n * HF + k] = __float2bfloat16(w1[k * HID + n]);
        }
    }
}

// ================= feature GEMM via mma.sync bf16 (hi/lo corrected, K3=768) ========
// C[M, 256] = h3 @ w3t^T per path. Block tile 128x128, 8 warps (4Mx2N).
__global__ __launch_bounds__(256) void gemm_mma_k() {
    __shared__ __align__(16) char sA[16384];   // 128 rows x 128B (64 bf16 k-slice)
    __shared__ __align__(16) char sB[16384];
    const int tid = threadIdx.x;
    const int wid = tid >> 5, lane = tid & 31;
    const int wm = wid & 3, wn = wid >> 2;
    const int row0 = blockIdx.y * 128;
    const int col0 = blockIdx.x * 128;
    const int p = blockIdx.z;

    const uint4* A = (const uint4*)g_h3;                                 // 96 uint4/row
    const uint4* B = (const uint4*)(g_w3t + (size_t)p * HF * K3);

    float c[2][8][4];
    #pragma unroll
    for (int a = 0; a < 2; a++)
        #pragma unroll
        for (int b = 0; b < 8; b++)
            #pragma unroll
            for (int q = 0; q < 4; q++) c[a][b][q] = 0.f;

    const uint32_t sAb = smem_u32(sA), sBb = smem_u32(sB);

    for (int kc = 0; kc < 12; kc++) {
        #pragma unroll
        for (int i = tid; i < 1024; i += 256) {
            int r = i >> 3, q = i & 7;
            uint32_t so = SWZ128((uint32_t)(r * 128 + q * 16));
            int gr = row0 + r;
            uint4 v = make_uint4(0u, 0u, 0u, 0u);
            if (gr < N_NODES) v = A[(size_t)gr * 96 + kc * 8 + q];
            *(uint4*)(sA + so) = v;
            *(uint4*)(sB + so) = B[(size_t)(col0 + r) * 96 + kc * 8 + q];
        }
        __syncthreads();
        #pragma unroll
        for (int ks = 0; ks < 4; ks++) {
            const int k0 = ks * 16;
            uint32_t a[2][4], b[4][4];
            #pragma unroll
            for (int fm = 0; fm < 2; fm++) {
                int row = wm * 32 + fm * 16 + ((lane >> 3) & 1) * 8 + (lane & 7);
                int kcol = k0 + (lane >> 4) * 8;
                ldsm_x4(a[fm][0], a[fm][1], a[fm][2], a[fm][3],
                        sAb + SWZ128((uint32_t)(row * 128 + kcol * 2)));
            }
            #pragma unroll
            for (int fp = 0; fp < 4; fp++) {
                int nrow = wn * 64 + fp * 16 + (lane >> 4) * 8 + (lane & 7);
                int kcol = k0 + ((lane >> 3) & 1) * 8;
                ldsm_x4(b[fp][0], b[fp][1], b[fp][2], b[fp][3],
                        sBb + SWZ128((uint32_t)(nrow * 128 + kcol * 2)));
            }
            #pragma unroll
            for (int fm = 0; fm < 2; fm++)
                #pragma unroll
                for (int fn = 0; fn < 8; fn++)
                    mma16816(c[fm][fn], a[fm], b[fn >> 1][(fn & 1) * 2], b[fn >> 1][(fn & 1) * 2 + 1]);
        }
        __syncthreads();
    }

    float* outp = g_xw + (size_t)p * N_NODES * HF;
    #pragma unroll
    for (int fm = 0; fm < 2; fm++) {
        int rbase = row0 + wm * 32 + fm * 16 + (lane >> 2);
        #pragma unroll
        for (int half = 0; half < 2; half++) {
            int grow = rbase + half * 8;
            if (grow < N_NODES) {
                #pragma unroll
                for (int fn = 0; fn < 8; fn++) {
                    int col = col0 + wn * 64 + fn * 8 + (lane & 3) * 2;
                    float2 v = make_float2(c[fm][fn][half * 2], c[fm][fn][half * 2 + 1]);
                    *(float2*)(outp + (size_t)grow * HF + col) = v;
                }
            }
        }
    }
}

// ================= alpha =================
__global__ void alpha_k(const float* __restrict__ asrc, const float* __restrict__ adst) {
    int idx = blockIdx.x * blockDim.x + threadIdx.x;
    if (idx >= NPN * NH) return;
    int ng = idx >> 2, h = idx & 3;
    int p = ng / N_NODES;
    const float* xr = g_xw + (size_t)ng * HF + h * FD;
    const float* sa = asrc + p * NH * FD + h * FD;
    const float* da = adst + p * NH * FD + h * FD;
    float ss = 0.f, sd = 0.f;
    #pragma unroll
    for (int f4 = 0; f4 < FD; f4 += 4) {
        float4 x = *(const float4*)(xr + f4);
        float4 a = *(const float4*)(sa + f4);
        float4 d = *(const float4*)(da + f4);
        ss += x.x * a.x + x.y * a.y + x.z * a.z + x.w * a.w;
        sd += x.x * d.x + x.y * d.y + x.z * d.z + x.w * d.w;
    }
    g_as[idx] = ss;
    g_ad[idx] = sd;
}

// ================= CSR aggregation (writes fp32 z + bf16 zb) =================
#define CHUNK 128
__global__ __launch_bounds__(64) void agg_k(const float* __restrict__ bias_all) {
    const int n = blockIdx.x;
    const int p = blockIdx.y;
    const int t = threadIdx.x;
    __shared__ int    s_src[CHUNK];
    __shared__ float4 s_w[CHUNK];
    __shared__ float4 s_red[64];

    const size_t ng = (size_t)p * N_NODES + n;
    const int beg = g_off[ng];
    const int end = g_cur[ng];
    const float4 ad4 = *(const float4*)&g_ad[ng * NH];
    const float4 asn = *(const float4*)&g_as[ng * NH];
    const float* asp = g_as + (size_t)p * N_NODES * NH;
    const float* xwp = g_xw + (size_t)p * N_NODES * HF;

    float4 acc = make_float4(0.f, 0.f, 0.f, 0.f);
    for (int j = beg + t; j < end; j += 64) {
        int src = g_srcs[j];
        float4 a = *(const float4*)&asp[src * NH];
        acc.x += __expf(lrelu(a.x + ad4.x));
        acc.y += __expf(lrelu(a.y + ad4.y));
        acc.z += __expf(lrelu(a.z + ad4.z));
        acc.w += __expf(lrelu(a.w + ad4.w));
    }
    s_red[t] = acc;
    __syncthreads();
    #pragma unroll
    for (int o = 32; o > 0; o >>= 1) {
        if (t < o) {
            float4 b = s_red[t + o]; float4 a = s_red[t];
            a.x += b.x; a.y += b.y; a.z += b.z; a.w += b.w;
            s_red[t] = a;
        }
        __syncthreads();
    }
    float4 es;
    es.x = __expf(lrelu(asn.x + ad4.x));
    es.y = __expf(lrelu(asn.y + ad4.y));
    es.z = __expf(lrelu(asn.z + ad4.z));
    es.w = __expf(lrelu(asn.w + ad4.w));
    float4 sden = s_red[0];
    float4 inv4;
    inv4.x = 1.f / (sden.x + es.x);
    inv4.y = 1.f / (sden.y + es.y);
    inv4.z = 1.f / (sden.z + es.z);
    inv4.w = 1.f / (sden.w + es.w);
    __syncthreads();

    const int c = t * 4;
    const int head = c >> 6;
    const float invh = ((const float*)&inv4)[head];
    const float selfw = ((const float*)&es)[head] * invh;

    float4 x4 = *(const float4*)(xwp + (size_t)n * HF + c);
    float4 accz;
    accz.x = selfw * x4.x; accz.y = selfw * x4.y;
    accz.z = selfw * x4.z; accz.w = selfw * x4.w;

    for (int base = beg; base < end; base += CHUNK) {
        int cn = min(CHUNK, end - base);
        for (int jj = t; jj < cn; jj += 64) {
            int src = g_srcs[base + jj];
            s_src[jj] = src;
            float4 a = *(const float4*)&asp[src * NH];
            float4 w;
            w.x = __expf(lrelu(a.x + ad4.x)) * inv4.x;
            w.y = __expf(lrelu(a.y + ad4.y)) * inv4.y;
            w.z = __expf(lrelu(a.z + ad4.z)) * inv4.z;
            w.w = __expf(lrelu(a.w + ad4.w)) * inv4.w;
            s_w[jj] = w;
        }
        __syncthreads();
        for (int jj = 0; jj < cn; jj++) {
            float ww = ((const float*)&s_w[jj])[head];
            float4 x = *(const float4*)(xwp + (size_t)s_src[jj] * HF + c);
            accz.x += ww * x.x; accz.y += ww * x.y;
            accz.z += ww * x.z; accz.w += ww * x.w;
        }
        __syncthreads();
    }

    float4 b4 = *(const float4*)(bias_all + p * HF + c);
    accz.x += b4.x; accz.y += b4.y; accz.z += b4.z; accz.w += b4.w;
    *(float4*)(g_z + ng * HF + c) = accz;

    __nv_bfloat162 h01 = __floats2bfloat162_rn(accz.x, accz.y);
    __nv_bfloat162 h23 = __floats2bfloat162_rn(accz.z, accz.w);
    *(uint2*)(g_zb + ng * HF + c) = make_uint2(*(uint32_t*)&h01, *(uint32_t*)&h23);
}

// ================= semantic GEMM (pure bf16, K=256) + fused tanh-dot-reduce =====
__global__ __launch_bounds__(256) void sem_mma_k(const float* __restrict__ b1,
                                                 const float* __restrict__ w2) {
    __shared__ __align__(16) char sA[16384];
    __shared__ __align__(16) char sB[16384];
    __shared__ float s_b1[HID], s_w2[HID], s_acc[NP];
    const int tid = threadIdx.x;
    const int wid = tid >> 5, lane = tid & 31;
    const int wm = wid & 3, wn = wid >> 2;
    const int row0 = blockIdx.x * 128;

    if (tid < NP) s_acc[tid] = 0.f;
    if (tid < HID) { s_b1[tid] = b1[tid]; s_w2[tid] = w2[tid]; }

    const uint4* A = (const uint4*)g_zb;    // 32 uint4/row
    const uint4* B = (const uint4*)g_w1t;   // 32 uint4/row, 128 rows

    float c[2][8][4];
    #pragma unroll
    for (int a = 0; a < 2; a++)
        #pragma unroll
        for (int b = 0; b < 8; b++)
            #pragma unroll
            for (int q = 0; q < 4; q++) c[a][b][q] = 0.f;

    const uint32_t sAb = smem_u32(sA), sBb = smem_u32(sB);

    for (int kc = 0; kc < 4; kc++) {
        #pragma unroll
        for (int i = tid; i < 1024; i += 256) {
            int r = i >> 3, q = i & 7;
            uint32_t so = SWZ128((uint32_t)(r * 128 + q * 16));
            int gr = row0 + r;
            uint4 v = make_uint4(0u, 0u, 0u, 0u);
            if (gr < NPN) v = A[(size_t)gr * 32 + kc * 8 + q];
            *(uint4*)(sA + so) = v;
            *(uint4*)(sB + so) = B[(size_t)r * 32 + kc * 8 + q];
        }
        __syncthreads();
        #pragma unroll
        for (int ks = 0; ks < 4; ks++) {
            const int k0 = ks * 16;
            uint32_t a[2][4], b[4][4];
            #pragma unroll
            for (int fm = 0; fm < 2; fm++) {
                int row = wm * 32 + fm * 16 + ((lane >> 3) & 1) * 8 + (lane & 7);
                int kcol = k0 + (lane >> 4) * 8;
                ldsm_x4(a[fm][0], a[fm][1], a[fm][2], a[fm][3],
                        sAb + SWZ128((uint32_t)(row * 128 + kcol * 2)));
            }
            #pragma unroll
            for (int fp = 0; fp < 4; fp++) {
                int nrow = wn * 64 + fp * 16 + (lane >> 4) * 8 + (lane & 7);
                int kcol = k0 + ((lane >> 3) & 1) * 8;
                ldsm_x4(b[fp][0], b[fp][1], b[fp][2], b[fp][3],
                        sBb + SWZ128((uint32_t)(nrow * 128 + kcol * 2)));
            }
            #pragma unroll
            for (int fm = 0; fm < 2; fm++)
                #pragma unroll
                for (int fn = 0; fn < 8; fn++)
                    mma16816(c[fm][fn], a[fm], b[fn >> 1][(fn & 1) * 2], b[fn >> 1][(fn & 1) * 2 + 1]);
        }
        __syncthreads();
    }

    // epilogue: v = tanh(c + b1) . w2, reduced per path
    #pragma unroll
    for (int fm = 0; fm < 2; fm++) {
        int rbase = row0 + wm * 32 + fm * 16 + (lane >> 2);
        #pragma unroll
        for (int half = 0; half < 2; half++) {
            int grow = rbase + half * 8;
            float v = 0.f;
            #pragma unroll
            for (int fn = 0; fn < 8; fn++) {
                int col = wn * 64 + fn * 8 + (lane & 3) * 2;
                v += tanhf(c[fm][fn][half * 2]     + s_b1[col])     * s_w2[col];
                v += tanhf(c[fm][fn][half * 2 + 1] + s_b1[col + 1]) * s_w2[col + 1];
            }
            v += __shfl_xor_sync(0xffffffffu, v, 1);
            v += __shfl_xor_sync(0xffffffffu, v, 2);
            if ((lane & 3) == 0 && grow < NPN)
                atomicAdd(&s_acc[grow / N_NODES], v);
        }
    }
    __syncthreads();
    if (tid < NP) atomicAdd(&g_wsum[tid], s_acc[tid]);
}

// ================= final combine =================
__global__ void final_k(float* __restrict__ out) {
    int idx = blockIdx.x * blockDim.x + threadIdx.x;
    if (idx >= N_NODES * (HF / 4)) return;
    float m0 = g_wsum[0] * (1.f / N_NODES);
    float m1 = g_wsum[1] * (1.f / N_NODES);
    float m2 = g_wsum[2] * (1.f / N_NODES);
    float mm = fmaxf(m0, fmaxf(m1, m2));
    float e0 = __expf(m0 - mm), e1 = __expf(m1 - mm), e2 = __expf(m2 - mm);
    float inv = 1.f / (e0 + e1 + e2);
    float b0 = e0 * inv, b1 = e1 * inv, b2 = e2 * inv;
    size_t off = (size_t)idx * 4;
    float4 z0 = *(const float4*)(g_z + off);
    float4 z1 = *(const float4*)(g_z + (size_t)N_NODES * HF + off);
    float4 z2 = *(const float4*)(g_z + (size_t)2 * N_NODES * HF + off);
    float4 o;
    o.x = b0 * z0.x + b1 * z1.x + b2 * z2.x;
    o.y = b0 * z0.y + b1 * z1.y + b2 * z2.y;
    o.z = b0 * z0.z + b1 * z1.z + b2 * z2.z;
    o.w = b0 * z0.w + b1 * z1.w + b2 * z2.w;
    *(float4*)(out + off) = o;
}

// ================= launch =================
extern "C" void kernel_launch(void* const* d_in, const int* in_sizes, int n_in,
                              void* d_out, int out_size) {
    const float* h        = (const float*)d_in[0];
    const int* e0         = (const int*)d_in[1];
    const int* e1         = (const int*)d_in[2];
    const int* e2         = (const int*)d_in[3];
    const float* gat_W    = (const float*)d_in[4];
    const float* att_src  = (const float*)d_in[5];
    const float* att_dst  = (const float*)d_in[6];
    const float* gat_bias = (const float*)d_in[7];
    const float* sa_w1    = (const float*)d_in[8];
    const float* sa_b1    = (const float*)d_in[9];
    const float* sa_w2    = (const float*)d_in[10];
    float* out = (float*)d_out;

    zero_k<<<(NPN + 255) / 256, 256>>>();
    hist_k<<<(NP * E_EDGES + 255) / 256, 256>>>(e0, e1, e2);
    scan_k<<<1, 1024>>>();
    scatter_k<<<(NP * E_EDGES + 255) / 256, 256>>>(e0, e1, e2);

    conv_h_k<<<(N_NODES * DIN + 255) / 256, 256>>>(h);
    conv_w_k<<<(NP * DIN * HF + HID * HF + 255) / 256, 256>>>(gat_W, sa_w1);

    dim3 ggrid(HF / 128, (N_NODES + 127) / 128, NP);
    gemm_mma_k<<<ggrid, 256>>>();

    alpha_k<<<(NPN * NH + 255) / 256, 256>>>(att_src, att_dst);

    dim3 agrid(N_NODES, NP);
    agg_k<<<agrid, 64>>>(gat_bias);

    sem_mma_k<<<(NPN + 127) / 128, 256>>>(sa_b1, sa_w2);

    final_k<<<(N_NODES * (HF / 4) + 255) / 256, 256>>>(out);
}

// round 10
// speedup vs baseline: 3.8511x; 1.1728x over previous
#include <cuda_runtime.h>
#include <cuda_bf16.h>
#include <cstdint>

#define N_NODES 50000
#define E_EDGES 400000
#define DIN     256
#define HF      256
#define NH      4
#define FD      64
#define NP      3
#define HID     128
#define NEG     0.2f
#define NPN     (NP * N_NODES)
#define K3      768     // [hi | lo | hi] concatenated K for feature GEMM

// ================= scratch (static device globals) =================
__device__ __align__(16) float g_xw[(size_t)NP * N_NODES * HF];
__device__ __align__(16) float g_z [(size_t)NP * N_NODES * HF];
__device__ __align__(16) float g_as[NPN * NH];
__device__ __align__(16) float g_ad[NPN * NH];
__device__ int   g_cnt[NPN];
__device__ int   g_off[NPN];
__device__ int   g_cur[NPN];
__device__ int   g_srcs[(size_t)NP * E_EDGES];
__device__ float g_wsum[NP];
__device__ __align__(16) __nv_bfloat16 g_h3 [(size_t)N_NODES * K3];   // h  [hi|lo|hi]
__device__ __align__(16) __nv_bfloat16 g_w3t[(size_t)NP * HF * K3];   // W^T [hi|hi|lo]
__device__ __align__(16) __nv_bfloat16 g_w1t[(size_t)HID * HF];       // w1^T bf16 [n][k]
__device__ __align__(16) __nv_bfloat16 g_zb [(size_t)NPN * HF];       // z bf16

__device__ __forceinline__ float lrelu(float x) { return x > 0.f ? x : NEG * x; }
__device__ __forceinline__ uint32_t smem_u32(const void* p) {
    uint32_t a;
    asm("{ .reg .u64 t; cvta.to.shared.u64 t, %1; cvt.u32.u64 %0, t; }" : "=r"(a) : "l"(p));
    return a;
}
#define SWZ128(o) ((o) ^ (((o) >> 3) & 0x70))
#define CP_ASYNC16(sm, gm) \
    asm volatile("cp.async.cg.shared.global [%0], [%1], 16;" :: "r"(sm), "l"(gm) : "memory")
#define CP_COMMIT()   asm volatile("cp.async.commit_group;" ::: "memory")
#define CP_WAIT(N)    asm volatile("cp.async.wait_group %0;" :: "n"(N) : "memory")

__device__ __forceinline__ void ldsm_x4(uint32_t& r0, uint32_t& r1, uint32_t& r2, uint32_t& r3,
                                        uint32_t addr) {
    asm volatile("ldmatrix.sync.aligned.m8n8.x4.shared.b16 {%0,%1,%2,%3}, [%4];"
                 : "=r"(r0), "=r"(r1), "=r"(r2), "=r"(r3) : "r"(addr));
}
__device__ __forceinline__ void mma16816(float* c, const uint32_t* a, uint32_t b0, uint32_t b1) {
    asm volatile("mma.sync.aligned.m16n8k16.row.col.f32.bf16.bf16.f32 "
                 "{%0,%1,%2,%3}, {%4,%5,%6,%7}, {%8,%9}, {%0,%1,%2,%3};"
                 : "+f"(c[0]), "+f"(c[1]), "+f"(c[2]), "+f"(c[3])
                 : "r"(a[0]), "r"(a[1]), "r"(a[2]), "r"(a[3]), "r"(b0), "r"(b1));
}

// ================= CSR setup =================
__global__ void zero_k() {
    int i = blockIdx.x * blockDim.x + threadIdx.x;
    if (i < NPN) g_cnt[i] = 0;
    if (i < NP) g_wsum[i] = 0.f;
}
__global__ void hist_k(const int* __restrict__ e0, const int* __restrict__ e1,
                       const int* __restrict__ e2) {
    int idx = blockIdx.x * blockDim.x + threadIdx.x;
    if (idx >= NP * E_EDGES) return;
    int p = idx / E_EDGES, e = idx - p * E_EDGES;
    const int* ei = (p == 0) ? e0 : (p == 1) ? e1 : e2;
    atomicAdd(&g_cnt[p * N_NODES + ei[E_EDGES + e]], 1);
}
__global__ __launch_bounds__(1024) void scan_k() {
    __shared__ int sums[1024];
    const int t = threadIdx.x;
    const int chunk = (NPN + 1023) / 1024;
    int b = t * chunk, e = min(b + chunk, NPN);
    int s = 0;
    for (int i = b; i < e; i++) s += g_cnt[i];
    sums[t] = s;
    __syncthreads();
    for (int o = 1; o < 1024; o <<= 1) {
        int v = (t >= o) ? sums[t - o] : 0;
        __syncthreads();
        sums[t] += v;
        __syncthreads();
    }
    int run = (t == 0) ? 0 : sums[t - 1];
    for (int i = b; i < e; i++) {
        int c = g_cnt[i];
        g_off[i] = run; g_cur[i] = run; run += c;
    }
}
__global__ void scatter_k(const int* __restrict__ e0, const int* __restrict__ e1,
                          const int* __restrict__ e2) {
    int idx = blockIdx.x * blockDim.x + threadIdx.x;
    if (idx >= NP * E_EDGES) return;
    int p = idx / E_EDGES, e = idx - p * E_EDGES;
    const int* ei = (p == 0) ? e0 : (p == 1) ? e1 : e2;
    int pos = atomicAdd(&g_cur[p * N_NODES + ei[E_EDGES + e]], 1);
    g_srcs[pos] = ei[e];
}

// ================= fp32 -> bf16 split conversions =================
__global__ void conv_h_k(const float* __restrict__ h) {
    int i = blockIdx.x * blockDim.x + threadIdx.x;
    if (i >= N_NODES * DIN) return;
    int row = i >> 8, k = i & 255;
    float f = h[i];
    __nv_bfloat16 hi = __float2bfloat16(f);
    __nv_bfloat16 lo = __float2bfloat16(f - __bfloat162float(hi));
    size_t base = (size_t)row * K3 + k;
    g_h3[base] = hi;
    g_h3[base + 256] = lo;
    g_h3[base + 512] = hi;
}
__global__ void conv_w_k(const float* __restrict__ W, const float* __restrict__ w1) {
    int i = blockIdx.x * blockDim.x + threadIdx.x;
    if (i < NP * DIN * HF) {
        int p = i >> 16, rem = i & 65535, n = rem >> 8, k = rem & 255;
        float f = W[p * 65536 + k * 256 + n];
        __nv_bfloat16 hi = __float2bfloat16(f);
        __nv_bfloat16 lo = __float2bfloat16(f - __bfloat162float(hi));
        size_t base = (size_t)p * HF * K3 + (size_t)n * K3 + k;
        g_w3t[base] = hi;
        g_w3t[base + 256] = hi;
        g_w3t[base + 512] = lo;
    } else {
        int j = i - NP * DIN * HF;
        if (j < HID * HF) {
            int n = j >> 8, k = j & 255;
            g_w1t[(size_t)n * HF + k] = __float2bfloat16(w1[k * HID + n]);
        }
    }
}

// ================= feature GEMM: mma.sync bf16, cp.async double-buffered =========
__global__ __launch_bounds__(256) void gemm_mma_k() {
    __shared__ __align__(16) char sA[2][16384];
    __shared__ __align__(16) char sB[2][16384];
    const int tid = threadIdx.x;
    const int wid = tid >> 5, lane = tid & 31;
    const int wm = wid & 3, wn = wid >> 2;
    const int row0 = blockIdx.y * 128;
    const int col0 = blockIdx.x * 128;
    const int p = blockIdx.z;

    const char* Ag = (const char*)g_h3;
    const char* Bg = (const char*)(g_w3t + (size_t)p * HF * K3);

    float c[2][8][4];
    #pragma unroll
    for (int a = 0; a < 2; a++)
        #pragma unroll
        for (int b = 0; b < 8; b++)
            #pragma unroll
            for (int q = 0; q < 4; q++) c[a][b][q] = 0.f;

    const uint32_t sAb0 = smem_u32(sA[0]), sBb0 = smem_u32(sB[0]);

    // loader: 1024 uint4 per tile / 256 threads = 4 per thread per tile
    auto load_tile = [&](int kc, int buf) {
        #pragma unroll
        for (int u = 0; u < 4; u++) {
            int i = tid + u * 256;
            int r = i >> 3, q = i & 7;
            uint32_t so = SWZ128((uint32_t)(r * 128 + q * 16));
            int gr = row0 + r;
            uint32_t sa = sAb0 + buf * 16384 + so;
            if (gr < N_NODES)
                CP_ASYNC16(sa, Ag + (size_t)gr * 1536 + kc * 128 + q * 16);
            else
                *(uint4*)(sA[buf] + so) = make_uint4(0u, 0u, 0u, 0u);
            CP_ASYNC16(sBb0 + buf * 16384 + so, Bg + (size_t)(col0 + r) * 1536 + kc * 128 + q * 16);
        }
    };

    load_tile(0, 0);
    CP_COMMIT();

    for (int kc = 0; kc < 12; kc++) {
        const int cur = kc & 1;
        if (kc + 1 < 12) {
            load_tile(kc + 1, cur ^ 1);
            CP_COMMIT();
            CP_WAIT(1);
        } else {
            CP_WAIT(0);
        }
        __syncthreads();
        const uint32_t sAb = sAb0 + cur * 16384;
        const uint32_t sBb = sBb0 + cur * 16384;
        #pragma unroll
        for (int ks = 0; ks < 4; ks++) {
            const int k0 = ks * 16;
            uint32_t a[2][4], b[4][4];
            #pragma unroll
            for (int fm = 0; fm < 2; fm++) {
                int row = wm * 32 + fm * 16 + ((lane >> 3) & 1) * 8 + (lane & 7);
                int kcol = k0 + (lane >> 4) * 8;
                ldsm_x4(a[fm][0], a[fm][1], a[fm][2], a[fm][3],
                        sAb + SWZ128((uint32_t)(row * 128 + kcol * 2)));
            }
            #pragma unroll
            for (int fp = 0; fp < 4; fp++) {
                int nrow = wn * 64 + fp * 16 + (lane >> 4) * 8 + (lane & 7);
                int kcol = k0 + ((lane >> 3) & 1) * 8;
                ldsm_x4(b[fp][0], b[fp][1], b[fp][2], b[fp][3],
                        sBb + SWZ128((uint32_t)(nrow * 128 + kcol * 2)));
            }
            #pragma unroll
            for (int fm = 0; fm < 2; fm++)
                #pragma unroll
                for (int fn = 0; fn < 8; fn++)
                    mma16816(c[fm][fn], a[fm], b[fn >> 1][(fn & 1) * 2], b[fn >> 1][(fn & 1) * 2 + 1]);
        }
        __syncthreads();
    }

    float* outp = g_xw + (size_t)p * N_NODES * HF;
    #pragma unroll
    for (int fm = 0; fm < 2; fm++) {
        int rbase = row0 + wm * 32 + fm * 16 + (lane >> 2);
        #pragma unroll
        for (int half = 0; half < 2; half++) {
            int grow = rbase + half * 8;
            if (grow < N_NODES) {
                #pragma unroll
                for (int fn = 0; fn < 8; fn++) {
                    int col = col0 + wn * 64 + fn * 8 + (lane & 3) * 2;
                    float2 v = make_float2(c[fm][fn][half * 2], c[fm][fn][half * 2 + 1]);
                    *(float2*)(outp + (size_t)grow * HF + col) = v;
                }
            }
        }
    }
}

// ================= alpha: warp per (path,node) row, coalesced =================
__global__ __launch_bounds__(256) void alpha_k(const float* __restrict__ asrc,
                                               const float* __restrict__ adst) {
    int warp = (blockIdx.x * blockDim.x + threadIdx.x) >> 5;
    int lane = threadIdx.x & 31;
    if (warp >= NPN) return;
    int p = warp / N_NODES;
    const float* xr = g_xw + (size_t)warp * HF + lane * 8;
    const float* sa = asrc + p * HF + lane * 8;
    const float* da = adst + p * HF + lane * 8;
    float4 x0 = *(const float4*)xr,        x1 = *(const float4*)(xr + 4);
    float4 a0 = *(const float4*)sa,        a1 = *(const float4*)(sa + 4);
    float4 d0 = *(const float4*)da,        d1 = *(const float4*)(da + 4);
    float ss = x0.x*a0.x + x0.y*a0.y + x0.z*a0.z + x0.w*a0.w
             + x1.x*a1.x + x1.y*a1.y + x1.z*a1.z + x1.w*a1.w;
    float sd = x0.x*d0.x + x0.y*d0.y + x0.z*d0.z + x0.w*d0.w
             + x1.x*d1.x + x1.y*d1.y + x1.z*d1.z + x1.w*d1.w;
    // reduce within each oct (8 lanes cover one head: 8*8=64 floats)
    #pragma unroll
    for (int o = 4; o > 0; o >>= 1) {
        ss += __shfl_down_sync(0xffffffffu, ss, o);
        sd += __shfl_down_sync(0xffffffffu, sd, o);
    }
    if ((lane & 7) == 0) {
        int h = lane >> 3;
        g_as[(size_t)warp * NH + h] = ss;
        g_ad[(size_t)warp * NH + h] = sd;
    }
}

// ================= CSR aggregation (weights cached in smem when deg<=CHUNK) =====
#define CHUNK 128
__global__ __launch_bounds__(64) void agg_k(const float* __restrict__ bias_all) {
    const int n = blockIdx.x;
    const int p = blockIdx.y;
    const int t = threadIdx.x;
    __shared__ int    s_src[CHUNK];
    __shared__ float4 s_w[CHUNK];
    __shared__ float4 s_red[64];

    const size_t ng = (size_t)p * N_NODES + n;
    const int beg = g_off[ng];
    const int end = g_cur[ng];
    const int deg = end - beg;
    const bool cached = (deg <= CHUNK);
    const float4 ad4 = *(const float4*)&g_ad[ng * NH];
    const float4 asn = *(const float4*)&g_as[ng * NH];
    const float* asp = g_as + (size_t)p * N_NODES * NH;
    const float* xwp = g_xw + (size_t)p * N_NODES * HF;

    // pass A: compute un-normalized weights; cache to smem when they fit
    float4 acc = make_float4(0.f, 0.f, 0.f, 0.f);
    for (int j = t; j < deg; j += 64) {
        int src = g_srcs[beg + j];
        float4 a = *(const float4*)&asp[src * NH];
        float4 w;
        w.x = __expf(lrelu(a.x + ad4.x));
        w.y = __expf(lrelu(a.y + ad4.y));
        w.z = __expf(lrelu(a.z + ad4.z));
        w.w = __expf(lrelu(a.w + ad4.w));
        acc.x += w.x; acc.y += w.y; acc.z += w.z; acc.w += w.w;
        if (cached) { s_src[j] = src; s_w[j] = w; }
    }
    s_red[t] = acc;
    __syncthreads();
    #pragma unroll
    for (int o = 32; o > 0; o >>= 1) {
        if (t < o) {
            float4 b = s_red[t + o]; float4 a = s_red[t];
            a.x += b.x; a.y += b.y; a.z += b.z; a.w += b.w;
            s_red[t] = a;
        }
        __syncthreads();
    }
    float4 es;
    es.x = __expf(lrelu(asn.x + ad4.x));
    es.y = __expf(lrelu(asn.y + ad4.y));
    es.z = __expf(lrelu(asn.z + ad4.z));
    es.w = __expf(lrelu(asn.w + ad4.w));
    float4 sden = s_red[0];
    float4 inv4;
    inv4.x = 1.f / (sden.x + es.x);
    inv4.y = 1.f / (sden.y + es.y);
    inv4.z = 1.f / (sden.z + es.z);
    inv4.w = 1.f / (sden.w + es.w);
    __syncthreads();

    const int c = t * 4;
    const int head = c >> 6;
    const float invh = ((const float*)&inv4)[head];
    const float selfw = ((const float*)&es)[head] * invh;

    float4 x4 = *(const float4*)(xwp + (size_t)n * HF + c);
    float4 accz;
    accz.x = selfw * x4.x; accz.y = selfw * x4.y;
    accz.z = selfw * x4.z; accz.w = selfw * x4.w;

    if (cached) {
        #pragma unroll 4
        for (int jj = 0; jj < deg; jj++) {
            float ww = ((const float*)&s_w[jj])[head] * invh;
            float4 x = *(const float4*)(xwp + (size_t)s_src[jj] * HF + c);
            accz.x += ww * x.x; accz.y += ww * x.y;
            accz.z += ww * x.z; accz.w += ww * x.w;
        }
    } else {
        for (int base = beg; base < end; base += CHUNK) {
            int cn = min(CHUNK, end - base);
            for (int jj = t; jj < cn; jj += 64) {
                int src = g_srcs[base + jj];
                s_src[jj] = src;
                float4 a = *(const float4*)&asp[src * NH];
                float4 w;
                w.x = __expf(lrelu(a.x + ad4.x)) * inv4.x;
                w.y = __expf(lrelu(a.y + ad4.y)) * inv4.y;
                w.z = __expf(lrelu(a.z + ad4.z)) * inv4.z;
                w.w = __expf(lrelu(a.w + ad4.w)) * inv4.w;
                s_w[jj] = w;
            }
            __syncthreads();
            #pragma unroll 4
            for (int jj = 0; jj < cn; jj++) {
                float ww = ((const float*)&s_w[jj])[head];
                float4 x = *(const float4*)(xwp + (size_t)s_src[jj] * HF + c);
                accz.x += ww * x.x; accz.y += ww * x.y;
                accz.z += ww * x.z; accz.w += ww * x.w;
            }
            __syncthreads();
        }
    }

    float4 b4 = *(const float4*)(bias_all + p * HF + c);
    accz.x += b4.x; accz.y += b4.y; accz.z += b4.z; accz.w += b4.w;
    *(float4*)(g_z + ng * HF + c) = accz;

    __nv_bfloat162 h01 = __floats2bfloat162_rn(accz.x, accz.y);
    __nv_bfloat162 h23 = __floats2bfloat162_rn(accz.z, accz.w);
    *(uint2*)(g_zb + ng * HF + c) = make_uint2(*(uint32_t*)&h01, *(uint32_t*)&h23);
}

// ================= semantic GEMM (bf16, cp.async double-buffered) =================
__global__ __launch_bounds__(256) void sem_mma_k(const float* __restrict__ b1,
                                                 const float* __restrict__ w2) {
    __shared__ __align__(16) char sA[2][16384];
    __shared__ __align__(16) char sB[2][16384];
    __shared__ float s_b1[HID], s_w2[HID], s_acc[NP];
    const int tid = threadIdx.x;
    const int wid = tid >> 5, lane = tid & 31;
    const int wm = wid & 3, wn = wid >> 2;
    const int row0 = blockIdx.x * 128;

    if (tid < NP) s_acc[tid] = 0.f;
    if (tid < HID) { s_b1[tid] = b1[tid]; s_w2[tid] = w2[tid]; }

    const char* Ag = (const char*)g_zb;
    const char* Bg = (const char*)g_w1t;

    float c[2][8][4];
    #pragma unroll
    for (int a = 0; a < 2; a++)
        #pragma unroll
        for (int b = 0; b < 8; b++)
            #pragma unroll
            for (int q = 0; q < 4; q++) c[a][b][q] = 0.f;

    const uint32_t sAb0 = smem_u32(sA[0]), sBb0 = smem_u32(sB[0]);

    auto load_tile = [&](int kc, int buf) {
        #pragma unroll
        for (int u = 0; u < 4; u++) {
            int i = tid + u * 256;
            int r = i >> 3, q = i & 7;
            uint32_t so = SWZ128((uint32_t)(r * 128 + q * 16));
            int gr = row0 + r;
            uint32_t sa = sAb0 + buf * 16384 + so;
            if (gr < NPN)
                CP_ASYNC16(sa, Ag + (size_t)gr * 512 + kc * 128 + q * 16);
            else
                *(uint4*)(sA[buf] + so) = make_uint4(0u, 0u, 0u, 0u);
            CP_ASYNC16(sBb0 + buf * 16384 + so, Bg + (size_t)r * 512 + kc * 128 + q * 16);
        }
    };

    load_tile(0, 0);
    CP_COMMIT();

    for (int kc = 0; kc < 4; kc++) {
        const int cur = kc & 1;
        if (kc + 1 < 4) {
            load_tile(kc + 1, cur ^ 1);
            CP_COMMIT();
            CP_WAIT(1);
        } else {
            CP_WAIT(0);
        }
        __syncthreads();
        const uint32_t sAb = sAb0 + cur * 16384;
        const uint32_t sBb = sBb0 + cur * 16384;
        #pragma unroll
        for (int ks = 0; ks < 4; ks++) {
            const int k0 = ks * 16;
            uint32_t a[2][4], b[4][4];
            #pragma unroll
            for (int fm = 0; fm < 2; fm++) {
                int row = wm * 32 + fm * 16 + ((lane >> 3) & 1) * 8 + (lane & 7);
                int kcol = k0 + (lane >> 4) * 8;
                ldsm_x4(a[fm][0], a[fm][1], a[fm][2], a[fm][3],
                        sAb + SWZ128((uint32_t)(row * 128 + kcol * 2)));
            }
            #pragma unroll
            for (int fp = 0; fp < 4; fp++) {
                int nrow = wn * 64 + fp * 16 + (lane >> 4) * 8 + (lane & 7);
                int kcol = k0 + ((lane >> 3) & 1) * 8;
                ldsm_x4(b[fp][0], b[fp][1], b[fp][2], b[fp][3],
                        sBb + SWZ128((uint32_t)(nrow * 128 + kcol * 2)));
            }
            #pragma unroll
            for (int fm = 0; fm < 2; fm++)
                #pragma unroll
                for (int fn = 0; fn < 8; fn++)
                    mma16816(c[fm][fn], a[fm], b[fn >> 1][(fn & 1) * 2], b[fn >> 1][(fn & 1) * 2 + 1]);
        }
        __syncthreads();
    }

    #pragma unroll
    for (int fm = 0; fm < 2; fm++) {
        int rbase = row0 + wm * 32 + fm * 16 + (lane >> 2);
        #pragma unroll
        for (int half = 0; half < 2; half++) {
            int grow = rbase + half * 8;
            float v = 0.f;
            #pragma unroll
            for (int fn = 0; fn < 8; fn++) {
                int col = wn * 64 + fn * 8 + (lane & 3) * 2;
                v += tanhf(c[fm][fn][half * 2]     + s_b1[col])     * s_w2[col];
                v += tanhf(c[fm][fn][half * 2 + 1] + s_b1[col + 1]) * s_w2[col + 1];
            }
            v += __shfl_xor_sync(0xffffffffu, v, 1);
            v += __shfl_xor_sync(0xffffffffu, v, 2);
            if ((lane & 3) == 0 && grow < NPN)
                atomicAdd(&s_acc[grow / N_NODES], v);
        }
    }
    __syncthreads();
    if (tid < NP) atomicAdd(&g_wsum[tid], s_acc[tid]);
}

// ================= final combine =================
__global__ void final_k(float* __restrict__ out) {
    int idx = blockIdx.x * blockDim.x + threadIdx.x;
    if (idx >= N_NODES * (HF / 4)) return;
    float m0 = g_wsum[0] * (1.f / N_NODES);
    float m1 = g_wsum[1] * (1.f / N_NODES);
    float m2 = g_wsum[2] * (1.f / N_NODES);
    float mm = fmaxf(m0, fmaxf(m1, m2));
    float e0 = __expf(m0 - mm), e1 = __expf(m1 - mm), e2 = __expf(m2 - mm);
    float inv = 1.f / (e0 + e1 + e2);
    float b0 = e0 * inv, b1 = e1 * inv, b2 = e2 * inv;
    size_t off = (size_t)idx * 4;
    float4 z0 = *(const float4*)(g_z + off);
    float4 z1 = *(const float4*)(g_z + (size_t)N_NODES * HF + off);
    float4 z2 = *(const float4*)(g_z + (size_t)2 * N_NODES * HF + off);
    float4 o;
    o.x = b0 * z0.x + b1 * z1.x + b2 * z2.x;
    o.y = b0 * z0.y + b1 * z1.y + b2 * z2.y;
    o.z = b0 * z0.z + b1 * z1.z + b2 * z2.z;
    o.w = b0 * z0.w + b1 * z1.w + b2 * z2.w;
    *(float4*)(out + off) = o;
}

// ================= launch =================
extern "C" void kernel_launch(void* const* d_in, const int* in_sizes, int n_in,
                              void* d_out, int out_size) {
    const float* h        = (const float*)d_in[0];
    const int* e0         = (const int*)d_in[1];
    const int* e1         = (const int*)d_in[2];
    const int* e2         = (const int*)d_in[3];
    const float* gat_W    = (const float*)d_in[4];
    const float* att_src  = (const float*)d_in[5];
    const float* att_dst  = (const float*)d_in[6];
    const float* gat_bias = (const float*)d_in[7];
    const float* sa_w1    = (const float*)d_in[8];
    const float* sa_b1    = (const float*)d_in[9];
    const float* sa_w2    = (const float*)d_in[10];
    float* out = (float*)d_out;

    cudaFuncSetAttribute(gemm_mma_k, cudaFuncAttributeMaxDynamicSharedMemorySize, 0);
    cudaFuncSetAttribute(sem_mma_k,  cudaFuncAttributeMaxDynamicSharedMemorySize, 0);

    zero_k<<<(NPN + 255) / 256, 256>>>();
    hist_k<<<(NP * E_EDGES + 255) / 256, 256>>>(e0, e1, e2);
    scan_k<<<1, 1024>>>();
    scatter_k<<<(NP * E_EDGES + 255) / 256, 256>>>(e0, e1, e2);

    conv_h_k<<<(N_NODES * DIN + 255) / 256, 256>>>(h);
    conv_w_k<<<(NP * DIN * HF + HID * HF + 255) / 256, 256>>>(gat_W, sa_w1);

    dim3 ggrid(HF / 128, (N_NODES + 127) / 128, NP);
    gemm_mma_k<<<ggrid, 256>>>();

    alpha_k<<<(NPN + 7) / 8, 256>>>(att_src, att_dst);

    dim3 agrid(N_NODES, NP);
    agg_k<<<agrid, 64>>>(gat_bias);

    sem_mma_k<<<(NPN + 127) / 128, 256>>>(sa_b1, sa_w2);

    final_k<<<(N_NODES * (HF / 4) + 255) / 256, 256>>>(out);
}